// round 4
// baseline (speedup 1.0000x reference)
#include <cuda_runtime.h>
#include <math.h>

static constexpr int N_NODES = 100000;
static constexpr int N_EDGES = 1600000;
static constexpr int D = 128;

// ---------------- scratch (device globals; no runtime allocation) ----------------
__device__ __align__(16) float g_nft[N_NODES * D];       // atom_features @ W2^T + b2
__device__ __align__(16) float g_oemb[N_NODES * D];      // out_emb
__device__ __align__(16) float g_gi[N_NODES * 384];
__device__ __align__(16) float g_gh[N_NODES * 384];
__device__ float g_logit[N_NODES];
__device__ float g_logit_src[N_NODES];
__device__ int   g_cnt[N_NODES];
__device__ int   g_start[N_NODES];
__device__ int   g_cursor[N_NODES];
__device__ __align__(8) int2 g_pack[N_EDGES];            // {src, bits(exp(score))}
__device__ int   g_counter;
__device__ int   g_is64;                                  // edge_index dtype flag

// GEMM source/dest selectors (so kernels address device globals directly)
enum BufId { BUF_EXT = 0, BUF_NFT = 1, BUF_OEMB = 2, BUF_GI = 3, BUF_GH = 4 };

__device__ __forceinline__ const float* src_ptr(int id, const float* ext) {
    switch (id) {
        case BUF_OEMB: return g_oemb;
        default:       return ext;
    }
}
__device__ __forceinline__ float* dst_ptr(int id) {
    switch (id) {
        case BUF_NFT:  return g_nft;
        case BUF_GI:   return g_gi;
        default:       return g_gh;
    }
}

// dtype-adaptive edge index load, defensively clamped to [0, N_NODES).
__device__ __forceinline__ int load_idx(const void* ei, long long i, int is64) {
    long long v = is64 ? reinterpret_cast<const long long*>(ei)[i]
                       : (long long)reinterpret_cast<const int*>(ei)[i];
    v = v < 0 ? 0 : (v >= N_NODES ? N_NODES - 1 : v);
    return (int)v;
}

// ---------------- small kernels ----------------
// also detects edge dtype: int64 node ids < 2^31 look like (v,0,v,0,...) as words
__global__ void k_zero(const int* __restrict__ eiw) {
    int i = blockIdx.x * blockDim.x + threadIdx.x;
    if (i < N_NODES) g_cnt[i] = 0;
    if (i == 0) {
        g_counter = 0;
        g_is64 = (eiw[1] == 0 && eiw[3] == 0 && eiw[5] == 0 && eiw[7] == 0) ? 1 : 0;
    }
}

// per-node dot products with w_d = W1[0:128], w_s = W1[128:256]
__global__ void k_logits(const float* __restrict__ A, const float* __restrict__ W1) {
    int gid = blockIdx.x * blockDim.x + threadIdx.x;
    int node = gid >> 5, lane = gid & 31;
    if (node >= N_NODES) return;
    float4 x  = reinterpret_cast<const float4*>(A)[node * 32 + lane];
    float4 wd = __ldg(reinterpret_cast<const float4*>(W1) + lane);
    float4 ws = __ldg(reinterpret_cast<const float4*>(W1) + 32 + lane);
    float d = x.x * wd.x + x.y * wd.y + x.z * wd.z + x.w * wd.w;
    float s = x.x * ws.x + x.y * ws.y + x.z * ws.z + x.w * ws.w;
#pragma unroll
    for (int o = 16; o; o >>= 1) {
        d += __shfl_xor_sync(0xffffffffu, d, o);
        s += __shfl_xor_sync(0xffffffffu, s, o);
    }
    if (lane == 0) { g_logit[node] = d; g_logit_src[node] = s; }
}

__global__ void k_count(const void* __restrict__ ei) {
    int e = blockIdx.x * blockDim.x + threadIdx.x;
    if (e >= N_EDGES) return;
    int is64 = g_is64;
    int dst = load_idx(ei, (long long)N_EDGES + e, is64);
    atomicAdd(&g_cnt[dst], 1);
}

__global__ void k_alloc() {
    int n = blockIdx.x * blockDim.x + threadIdx.x;
    if (n >= N_NODES) return;
    int c = g_cnt[n];
    int s = atomicAdd(&g_counter, c);
    g_start[n] = s;
    g_cursor[n] = s;
}

// score -> leakyrelu -> exp; bucket (src, e^s) by dst.
// NOTE: segment_max is skipped: the max subtraction cancels exactly in
// attn = e / denom, and scores here are O(1) so exp cannot overflow.
__global__ void k_fill(const void* __restrict__ ei, const float* __restrict__ b1) {
    int e = blockIdx.x * blockDim.x + threadIdx.x;
    if (e >= N_EDGES) return;
    int is64 = g_is64;
    int src = load_idx(ei, e, is64);
    int dst = load_idx(ei, (long long)N_EDGES + e, is64);
    float sc = g_logit[dst] + g_logit_src[src] + __ldg(b1);
    sc = sc > 0.f ? sc : 0.2f * sc;
    float es = expf(sc);
    int pos = atomicAdd(&g_cursor[dst], 1);
    if (pos < N_EDGES) g_pack[pos] = make_int2(src, __float_as_int(es));
}

// warp per node: denom + weighted gather-aggregate + ELU + deg select
__global__ void k_agg(const float* __restrict__ A) {
    int gid = blockIdx.x * blockDim.x + threadIdx.x;
    int node = gid >> 5, lane = gid & 31;
    if (node >= N_NODES) return;
    int s0 = g_start[node];
    int len = g_cnt[node];
    if (s0 + len > N_EDGES) len = N_EDGES - s0 > 0 ? N_EDGES - s0 : 0;

    float dsum = 0.f;
    for (int t = lane; t < len; t += 32) dsum += __int_as_float(g_pack[s0 + t].y);
#pragma unroll
    for (int o = 16; o; o >>= 1) dsum += __shfl_xor_sync(0xffffffffu, dsum, o);

    float4 out;
    if (len > 0) {
        float inv = 1.f / dsum;
        float ax = 0.f, ay = 0.f, az = 0.f, aw = 0.f;
        const float4* nf = reinterpret_cast<const float4*>(g_nft);
#pragma unroll 2
        for (int t = 0; t < len; ++t) {
            int2 p = g_pack[s0 + t];
            float w = __int_as_float(p.y) * inv;
            float4 v = nf[(size_t)p.x * 32 + lane];
            ax = fmaf(w, v.x, ax);
            ay = fmaf(w, v.y, ay);
            az = fmaf(w, v.z, az);
            aw = fmaf(w, v.w, aw);
        }
        out.x = ax > 0.f ? ax : (expf(ax) - 1.f);
        out.y = ay > 0.f ? ay : (expf(ay) - 1.f);
        out.z = az > 0.f ? az : (expf(az) - 1.f);
        out.w = aw > 0.f ? aw : (expf(aw) - 1.f);
    } else {
        out = reinterpret_cast<const float4*>(A)[node * 32 + lane];
    }
    reinterpret_cast<float4*>(g_oemb)[node * 32 + lane] = out;
}

// ---------------- tiled GEMM: C[n,m] = sum_k X[n,k]*W[m,k] + bias[m] ----------------
// K = 128 fixed. 128x128 tile, 256 threads, 8x8 per thread, packed f32x2 FMA
// pairing along K (even/odd partial sums, horizontal add in epilogue).
// smem layout: row-major [row][k], XOR swizzle at 8B (k-pair) granularity:
//   phys_float(row,k) = row*128 + (((k>>1) ^ ((row>>3)&15)) << 1) + (k&1)
union UPack { unsigned long long u; float2 f; };

__global__ __launch_bounds__(256, 1) void k_gemm(
    int srcId, const float* __restrict__ Xext,
    const float* __restrict__ W, const float* __restrict__ bias,
    int dstId, int nRows, int mCols)
{
    extern __shared__ float smem[];
    float* As = smem;            // 128*128 floats
    float* Bs = smem + 128 * 128;

    const float* __restrict__ X = src_ptr(srcId, Xext);
    float* __restrict__ C = dst_ptr(dstId);

    const int tid = threadIdx.x;
    const int rowBase = blockIdx.x * 128;
    const int colBase = blockIdx.y * 128;

#pragma unroll
    for (int it = 0; it < 16; ++it) {
        int fidx = it * 256 + tid;
        int r  = fidx >> 5;      // tile row (one row per warp)
        int c4 = fidx & 31;      // float4 index along k
        int s  = (r >> 3) & 15;
        int base = r * 128;
        int o0 = base + ((((2 * c4)    ) ^ s) << 1);
        int o1 = base + ((((2 * c4) + 1) ^ s) << 1);
        int gr = rowBase + r;
        float4 v = (gr < nRows) ? reinterpret_cast<const float4*>(X)[(size_t)gr * 32 + c4]
                                : make_float4(0.f, 0.f, 0.f, 0.f);
        *reinterpret_cast<float2*>(As + o0) = make_float2(v.x, v.y);
        *reinterpret_cast<float2*>(As + o1) = make_float2(v.z, v.w);
        float4 w = reinterpret_cast<const float4*>(W)[(size_t)(colBase + r) * 32 + c4];
        *reinterpret_cast<float2*>(Bs + o0) = make_float2(w.x, w.y);
        *reinterpret_cast<float2*>(Bs + o1) = make_float2(w.z, w.w);
    }
    __syncthreads();

    const int ty = tid >> 4;   // row group 0..15
    const int tx = tid & 15;   // col group 0..15

    unsigned long long acc[8][8];
#pragma unroll
    for (int i = 0; i < 8; ++i)
#pragma unroll
        for (int j = 0; j < 8; ++j) acc[i][j] = 0ull;

    const float* aRow = As + ty * 8 * 128;
    const float* bRow = Bs + tx * 8 * 128;

#pragma unroll 8
    for (int kk = 0; kk < 64; ++kk) {   // k-pair index
        unsigned long long a2[8], b2[8];
        const int ao = (kk ^ ty) << 1;
        const int bo = (kk ^ tx) << 1;
#pragma unroll
        for (int i = 0; i < 8; ++i)
            a2[i] = *reinterpret_cast<const unsigned long long*>(aRow + i * 128 + ao);
#pragma unroll
        for (int j = 0; j < 8; ++j)
            b2[j] = *reinterpret_cast<const unsigned long long*>(bRow + j * 128 + bo);
#pragma unroll
        for (int i = 0; i < 8; ++i)
#pragma unroll
            for (int j = 0; j < 8; ++j)
                asm("fma.rn.f32x2 %0, %1, %2, %3;"
                    : "=l"(acc[i][j])
                    : "l"(a2[i]), "l"(b2[j]), "l"(acc[i][j]));
    }

    float bj[8];
#pragma unroll
    for (int j = 0; j < 8; ++j) bj[j] = bias[colBase + tx * 8 + j];

#pragma unroll
    for (int i = 0; i < 8; ++i) {
        int gr = rowBase + ty * 8 + i;
        if (gr < nRows) {
            float o[8];
#pragma unroll
            for (int j = 0; j < 8; ++j) {
                UPack u; u.u = acc[i][j];
                o[j] = u.f.x + u.f.y + bj[j];
            }
            float* dst = C + (size_t)gr * mCols + colBase + tx * 8;
            *reinterpret_cast<float4*>(dst)     = make_float4(o[0], o[1], o[2], o[3]);
            *reinterpret_cast<float4*>(dst + 4) = make_float4(o[4], o[5], o[6], o[7]);
        }
    }
}

// ---------------- GRU gates ----------------
__device__ __forceinline__ float sigf(float x) { return 1.f / (1.f + expf(-x)); }

__global__ void k_gate(const float* __restrict__ A, float* __restrict__ out) {
    int gid = blockIdx.x * blockDim.x + threadIdx.x;
    int node = gid >> 5, lane = gid & 31;
    if (node >= N_NODES) return;
    const float4* gi = reinterpret_cast<const float4*>(g_gi + (size_t)node * 384);
    const float4* gh = reinterpret_cast<const float4*>(g_gh + (size_t)node * 384);
    float4 gir = gi[lane], giz = gi[32 + lane], gin = gi[64 + lane];
    float4 ghr = gh[lane], ghz = gh[32 + lane], ghn = gh[64 + lane];
    float4 h = reinterpret_cast<const float4*>(A)[node * 32 + lane];
    float4 res;
    {
        float r = sigf(gir.x + ghr.x), z = sigf(giz.x + ghz.x);
        float n = tanhf(gin.x + r * ghn.x);
        res.x = (1.f - z) * n + z * h.x;
    }
    {
        float r = sigf(gir.y + ghr.y), z = sigf(giz.y + ghz.y);
        float n = tanhf(gin.y + r * ghn.y);
        res.y = (1.f - z) * n + z * h.y;
    }
    {
        float r = sigf(gir.z + ghr.z), z = sigf(giz.z + ghz.z);
        float n = tanhf(gin.z + r * ghn.z);
        res.z = (1.f - z) * n + z * h.z;
    }
    {
        float r = sigf(gir.w + ghr.w), z = sigf(giz.w + ghz.w);
        float n = tanhf(gin.w + r * ghn.w);
        res.w = (1.f - z) * n + z * h.w;
    }
    reinterpret_cast<float4*>(out)[node * 32 + lane] = res;
}

// ---------------- launch ----------------
extern "C" void kernel_launch(void* const* d_in, const int* in_sizes, int n_in,
                              void* d_out, int out_size) {
    const float* A    = (const float*)d_in[0];
    const float* W1   = (const float*)d_in[1];
    const float* b1   = (const float*)d_in[2];
    const float* W2   = (const float*)d_in[3];
    const float* b2   = (const float*)d_in[4];
    const float* w_ih = (const float*)d_in[5];
    const float* w_hh = (const float*)d_in[6];
    const float* b_ih = (const float*)d_in[7];
    const float* b_hh = (const float*)d_in[8];
    const void*  ei   = d_in[9];
    float* out = (float*)d_out;

    cudaFuncSetAttribute(k_gemm, cudaFuncAttributeMaxDynamicSharedMemorySize, 131072);

    constexpr int RT = (N_NODES + 127) / 128;       // 782 row tiles
    constexpr int NODE_BLKS = (N_NODES + 255) / 256;
    constexpr int EDGE_BLKS = (N_EDGES + 255) / 256;
    constexpr int WARP_BLKS = (N_NODES * 32 + 255) / 256;

    k_zero<<<NODE_BLKS, 256>>>((const int*)ei);
    k_gemm<<<dim3(RT, 1), 256, 131072>>>(BUF_EXT, A, W2, b2, BUF_NFT, N_NODES, 128);
    k_logits<<<WARP_BLKS, 256>>>(A, W1);
    k_count<<<EDGE_BLKS, 256>>>(ei);
    k_alloc<<<NODE_BLKS, 256>>>();
    k_fill<<<EDGE_BLKS, 256>>>(ei, b1);
    k_agg<<<WARP_BLKS, 256>>>(A);
    k_gemm<<<dim3(RT, 3), 256, 131072>>>(BUF_OEMB, nullptr, w_ih, b_ih, BUF_GI, N_NODES, 384);
    k_gemm<<<dim3(RT, 3), 256, 131072>>>(BUF_EXT, A, w_hh, b_hh, BUF_GH, N_NODES, 384);
    k_gate<<<WARP_BLKS, 256>>>(A, out);
}

// round 7
// speedup vs baseline: 1.5837x; 1.5837x over previous
#include <cuda_runtime.h>
#include <cuda_bf16.h>
#include <math.h>

static constexpr int N_NODES = 100000;
static constexpr int N_EDGES = 1600000;
static constexpr int D = 128;

// ---------------- scratch (device globals; no runtime allocation) ----------------
__device__ __align__(16) float g_nft[N_NODES * D];        // atom_features @ W2^T + b2 (fp32)
__device__ __align__(16) float g_gi[N_NODES * 384];
__device__ __align__(16) float g_gh[N_NODES * 384];
__device__ __align__(16) __nv_bfloat16 g_ahi[N_NODES * D];   // A split
__device__ __align__(16) __nv_bfloat16 g_alo[N_NODES * D];
__device__ __align__(16) __nv_bfloat16 g_ohi[N_NODES * D];   // out_emb split
__device__ __align__(16) __nv_bfloat16 g_olo[N_NODES * D];
__device__ __align__(16) __nv_bfloat16 g_w2h[128 * D],  g_w2l[128 * D];
__device__ __align__(16) __nv_bfloat16 g_wih_h[384 * D], g_wih_l[384 * D];
__device__ __align__(16) __nv_bfloat16 g_whh_h[384 * D], g_whh_l[384 * D];
__device__ float g_logit[N_NODES];
__device__ float g_logit_src[N_NODES];
__device__ int   g_cnt[N_NODES];
__device__ int   g_start[N_NODES];
__device__ int   g_cursor[N_NODES];
__device__ __align__(8) int2 g_pack[N_EDGES];             // {src, bits(exp(score))}
__device__ int   g_counter;
__device__ int   g_is64;

// ---------------- bf16 split helper ----------------
__device__ __forceinline__ void cvt_store4(float4 v, __nv_bfloat16* hi, __nv_bfloat16* lo, long long i4) {
    __nv_bfloat16 h0 = __float2bfloat16(v.x), h1 = __float2bfloat16(v.y);
    __nv_bfloat16 h2 = __float2bfloat16(v.z), h3 = __float2bfloat16(v.w);
    __nv_bfloat16 l0 = __float2bfloat16(v.x - __bfloat162float(h0));
    __nv_bfloat16 l1 = __float2bfloat16(v.y - __bfloat162float(h1));
    __nv_bfloat16 l2 = __float2bfloat16(v.z - __bfloat162float(h2));
    __nv_bfloat16 l3 = __float2bfloat16(v.w - __bfloat162float(h3));
    uint2 hp, lp;
    hp.x = (unsigned)__bfloat16_as_ushort(h0) | ((unsigned)__bfloat16_as_ushort(h1) << 16);
    hp.y = (unsigned)__bfloat16_as_ushort(h2) | ((unsigned)__bfloat16_as_ushort(h3) << 16);
    lp.x = (unsigned)__bfloat16_as_ushort(l0) | ((unsigned)__bfloat16_as_ushort(l1) << 16);
    lp.y = (unsigned)__bfloat16_as_ushort(l2) | ((unsigned)__bfloat16_as_ushort(l3) << 16);
    reinterpret_cast<uint2*>(hi)[i4] = hp;
    reinterpret_cast<uint2*>(lo)[i4] = lp;
}

// dtype-adaptive edge index load, clamped to [0, N_NODES).
__device__ __forceinline__ int load_idx(const void* ei, long long i, int is64) {
    long long v = is64 ? reinterpret_cast<const long long*>(ei)[i]
                       : (long long)reinterpret_cast<const int*>(ei)[i];
    v = v < 0 ? 0 : (v >= N_NODES ? N_NODES - 1 : v);
    return (int)v;
}

// ---------------- small kernels ----------------
__global__ void k_zero(const int* __restrict__ eiw) {
    int i = blockIdx.x * blockDim.x + threadIdx.x;
    if (i < N_NODES) g_cnt[i] = 0;
    if (i == 0) {
        g_counter = 0;
        g_is64 = (eiw[1] == 0 && eiw[3] == 0 && eiw[5] == 0 && eiw[7] == 0) ? 1 : 0;
    }
}

__global__ void k_cvtA(const float* __restrict__ A) {
    int i = blockIdx.x * blockDim.x + threadIdx.x;
    if (i >= N_NODES * 32) return;
    cvt_store4(reinterpret_cast<const float4*>(A)[i], g_ahi, g_alo, i);
}

__global__ void k_cvtW(const float* __restrict__ W2, const float* __restrict__ wih,
                       const float* __restrict__ whh) {
    int i = blockIdx.x * blockDim.x + threadIdx.x;
    const int n2 = 128 * 32, nih = 384 * 32;
    if (i < n2)
        cvt_store4(reinterpret_cast<const float4*>(W2)[i], g_w2h, g_w2l, i);
    else if (i < n2 + nih)
        cvt_store4(reinterpret_cast<const float4*>(wih)[i - n2], g_wih_h, g_wih_l, i - n2);
    else if (i < n2 + 2 * nih)
        cvt_store4(reinterpret_cast<const float4*>(whh)[i - n2 - nih], g_whh_h, g_whh_l, i - n2 - nih);
}

__global__ void k_logits(const float* __restrict__ A, const float* __restrict__ W1) {
    int gid = blockIdx.x * blockDim.x + threadIdx.x;
    int node = gid >> 5, lane = gid & 31;
    if (node >= N_NODES) return;
    float4 x  = reinterpret_cast<const float4*>(A)[node * 32 + lane];
    float4 wd = __ldg(reinterpret_cast<const float4*>(W1) + lane);
    float4 ws = __ldg(reinterpret_cast<const float4*>(W1) + 32 + lane);
    float d = x.x * wd.x + x.y * wd.y + x.z * wd.z + x.w * wd.w;
    float s = x.x * ws.x + x.y * ws.y + x.z * ws.z + x.w * ws.w;
#pragma unroll
    for (int o = 16; o; o >>= 1) {
        d += __shfl_xor_sync(0xffffffffu, d, o);
        s += __shfl_xor_sync(0xffffffffu, s, o);
    }
    if (lane == 0) { g_logit[node] = d; g_logit_src[node] = s; }
}

__global__ void k_count(const void* __restrict__ ei) {
    int e = blockIdx.x * blockDim.x + threadIdx.x;
    if (e >= N_EDGES) return;
    atomicAdd(&g_cnt[load_idx(ei, (long long)N_EDGES + e, g_is64)], 1);
}

__global__ void k_alloc() {
    int n = blockIdx.x * blockDim.x + threadIdx.x;
    if (n >= N_NODES) return;
    int c = g_cnt[n];
    int s = atomicAdd(&g_counter, c);
    g_start[n] = s;
    g_cursor[n] = s;
}

// segment_max elided: cancels exactly in attn = e/denom; scores are O(1).
__global__ void k_fill(const void* __restrict__ ei, const float* __restrict__ b1) {
    int e = blockIdx.x * blockDim.x + threadIdx.x;
    if (e >= N_EDGES) return;
    int is64 = g_is64;
    int src = load_idx(ei, e, is64);
    int dst = load_idx(ei, (long long)N_EDGES + e, is64);
    float sc = g_logit[dst] + g_logit_src[src] + __ldg(b1);
    sc = sc > 0.f ? sc : 0.2f * sc;
    float es = expf(sc);
    int pos = atomicAdd(&g_cursor[dst], 1);
    if (pos < N_EDGES) g_pack[pos] = make_int2(src, __float_as_int(es));
}

// warp per node: denom + weighted gather + ELU + deg select; writes bf16 split oemb
__global__ void k_agg(const float* __restrict__ A) {
    int gid = blockIdx.x * blockDim.x + threadIdx.x;
    int node = gid >> 5, lane = gid & 31;
    if (node >= N_NODES) return;
    int s0 = g_start[node];
    int len = g_cnt[node];
    if (s0 + len > N_EDGES) len = N_EDGES - s0 > 0 ? N_EDGES - s0 : 0;

    float dsum = 0.f;
    for (int t = lane; t < len; t += 32) dsum += __int_as_float(g_pack[s0 + t].y);
#pragma unroll
    for (int o = 16; o; o >>= 1) dsum += __shfl_xor_sync(0xffffffffu, dsum, o);

    float4 out;
    if (len > 0) {
        float inv = 1.f / dsum;
        float ax = 0.f, ay = 0.f, az = 0.f, aw = 0.f;
        const float4* nf = reinterpret_cast<const float4*>(g_nft);
#pragma unroll 2
        for (int t = 0; t < len; ++t) {
            int2 p = g_pack[s0 + t];
            float w = __int_as_float(p.y) * inv;
            float4 v = nf[(size_t)p.x * 32 + lane];
            ax = fmaf(w, v.x, ax); ay = fmaf(w, v.y, ay);
            az = fmaf(w, v.z, az); aw = fmaf(w, v.w, aw);
        }
        out.x = ax > 0.f ? ax : (expf(ax) - 1.f);
        out.y = ay > 0.f ? ay : (expf(ay) - 1.f);
        out.z = az > 0.f ? az : (expf(az) - 1.f);
        out.w = aw > 0.f ? aw : (expf(aw) - 1.f);
    } else {
        out = reinterpret_cast<const float4*>(A)[node * 32 + lane];
    }
    cvt_store4(out, g_ohi, g_olo, (long long)node * 32 + lane);
}

// ---------------- HMMA GEMM (base-ISA mma.sync; tcgen05 unavailable at .target sm_100) --------
// C[n,m] = X[n,:].W[m,:] + bias[m] via 2-term bf16 split:
//   D = Xhi*Whi + Xhi*Wlo + Xlo*Whi  (fp32 register accum)
// 128x128 CTA tile, 8 warps (2x4), warp tile 64x32, mma.m16n8k16.
// smem: row = 256B (16 chunks of 16B), phys chunk = chunk ^ (row&7)  -> STS & LDSM conflict-free.

static constexpr int SM_AHI = 0;
static constexpr int SM_ALO = 32768;
static constexpr int SM_BHI = 65536;
static constexpr int SM_BLO = 98304;
static constexpr int SM_TOTAL = 131072;

__device__ __forceinline__ unsigned smem_u32(const void* p) {
    unsigned a;
    asm("{ .reg .u64 t; cvta.to.shared.u64 t, %1; cvt.u32.u64 %0, t; }" : "=r"(a) : "l"(p));
    return a;
}
__device__ __forceinline__ void ldsm4(unsigned& r0, unsigned& r1, unsigned& r2, unsigned& r3, unsigned a) {
    asm volatile("ldmatrix.sync.aligned.m8n8.x4.shared.b16 {%0,%1,%2,%3}, [%4];"
                 : "=r"(r0), "=r"(r1), "=r"(r2), "=r"(r3) : "r"(a));
}
__device__ __forceinline__ void mma16816(float* c, unsigned a0, unsigned a1, unsigned a2, unsigned a3,
                                         unsigned b0, unsigned b1) {
    asm volatile("mma.sync.aligned.m16n8k16.row.col.f32.bf16.bf16.f32 "
                 "{%0,%1,%2,%3}, {%4,%5,%6,%7}, {%8,%9}, {%0,%1,%2,%3};"
                 : "+f"(c[0]), "+f"(c[1]), "+f"(c[2]), "+f"(c[3])
                 : "r"(a0), "r"(a1), "r"(a2), "r"(a3), "r"(b0), "r"(b1));
}

__global__ __launch_bounds__(256, 1) void k_hmma(
    int srcId,            // 0 = A split, 1 = oemb split
    int wId,              // 0 = W2, 1 = w_ih, 2 = w_hh
    const float* __restrict__ bias,
    int dstId,            // 0 = nft, 1 = gi, 2 = gh
    int mCols)
{
    extern __shared__ __align__(128) char smem[];
    const int tid = threadIdx.x, wid = tid >> 5, lane = tid & 31;
    const unsigned sb = smem_u32(smem);
    const int rowBase = blockIdx.x * 128;
    const int colBase = blockIdx.y * 128;

    const uint4* Xh = reinterpret_cast<const uint4*>(srcId == 0 ? g_ahi : g_ohi);
    const uint4* Xl = reinterpret_cast<const uint4*>(srcId == 0 ? g_alo : g_olo);
    const uint4* Wh = reinterpret_cast<const uint4*>(wId == 0 ? g_w2h : (wId == 1 ? g_wih_h : g_whh_h));
    const uint4* Wl = reinterpret_cast<const uint4*>(wId == 0 ? g_w2l : (wId == 1 ? g_wih_l : g_whh_l));
    float* C = dstId == 0 ? g_nft : (dstId == 1 ? g_gi : g_gh);

    // ---- tile load: 128 rows x 16 chunks per tile, 4 tiles ----
#pragma unroll
    for (int it = 0; it < 8; ++it) {
        int lc  = it * 256 + tid;        // 0..2047
        int row = lc >> 4;
        int ch  = lc & 15;
        unsigned so = (unsigned)(row * 256 + ((ch ^ (row & 7)) << 4));
        int gr = rowBase + row;
        uint4 z = make_uint4(0, 0, 0, 0);
        uint4 vh = (gr < N_NODES) ? Xh[(size_t)gr * 16 + ch] : z;
        uint4 vl = (gr < N_NODES) ? Xl[(size_t)gr * 16 + ch] : z;
        *reinterpret_cast<uint4*>(smem + SM_AHI + so) = vh;
        *reinterpret_cast<uint4*>(smem + SM_ALO + so) = vl;
        uint4 wh = Wh[(size_t)(colBase + row) * 16 + ch];
        uint4 wl = Wl[(size_t)(colBase + row) * 16 + ch];
        *reinterpret_cast<uint4*>(smem + SM_BHI + so) = wh;
        *reinterpret_cast<uint4*>(smem + SM_BLO + so) = wl;
    }
    __syncthreads();

    const int warpRow = (wid >> 2) * 64;   // 0 or 64
    const int warpCol = (wid & 3) * 32;    // 0,32,64,96

    // ldmatrix lane-address components
    // A: lanes 0-15 rows (l&15), lanes 16-31 same rows / +1 chunk
    const int arow = warpRow + (lane & 15);          // + mi*16
    const int ahalf = lane >> 4;                     // chunk offset 0/1
    // B: groups of 8 lanes: g0: n0-7 k-chunk 0 | g1: n0-7 +1 | g2: n8-15 0 | g3: n8-15 +1
    const int bn = warpCol + ((lane >> 4) << 3) + (lane & 7);   // + q*16
    const int bhalf = (lane >> 3) & 1;

    float acc[4][4][4];
#pragma unroll
    for (int mi = 0; mi < 4; ++mi)
#pragma unroll
        for (int nj = 0; nj < 4; ++nj)
#pragma unroll
            for (int q = 0; q < 4; ++q) acc[mi][nj][q] = 0.f;

    const unsigned aBase[3] = { sb + SM_AHI, sb + SM_AHI, sb + SM_ALO };
    const unsigned bBase[3] = { sb + SM_BHI, sb + SM_BLO, sb + SM_BHI };

#pragma unroll
    for (int t = 0; t < 3; ++t) {
        unsigned ab = aBase[t], bb = bBase[t];
#pragma unroll
        for (int s = 0; s < 8; ++s) {
            unsigned a[4][4];
#pragma unroll
            for (int mi = 0; mi < 4; ++mi) {
                int r = arow + mi * 16;
                unsigned ch = (unsigned)((2 * s + ahalf) ^ (r & 7));
                ldsm4(a[mi][0], a[mi][1], a[mi][2], a[mi][3], ab + r * 256 + (ch << 4));
            }
            unsigned b[2][4];
#pragma unroll
            for (int q = 0; q < 2; ++q) {
                int n = bn + q * 16;
                unsigned ch = (unsigned)((2 * s + bhalf) ^ (n & 7));
                ldsm4(b[q][0], b[q][1], b[q][2], b[q][3], bb + n * 256 + (ch << 4));
            }
#pragma unroll
            for (int mi = 0; mi < 4; ++mi) {
#pragma unroll
                for (int nj = 0; nj < 4; ++nj) {
                    unsigned b0 = b[nj >> 1][(nj & 1) * 2];
                    unsigned b1 = b[nj >> 1][(nj & 1) * 2 + 1];
                    mma16816(acc[mi][nj], a[mi][0], a[mi][1], a[mi][2], a[mi][3], b0, b1);
                }
            }
        }
    }

    // ---- epilogue: bias + direct STG (c0,c1 at row, c2,c3 at row+8) ----
    const int colOff = colBase + warpCol + 2 * (lane & 3);
#pragma unroll
    for (int nj = 0; nj < 4; ++nj) {
        int c = colOff + nj * 8;
        float2 b2v = __ldg(reinterpret_cast<const float2*>(bias + c));
#pragma unroll
        for (int mi = 0; mi < 4; ++mi) {
            int r0 = rowBase + warpRow + mi * 16 + (lane >> 2);
            if (r0 < N_NODES)
                *reinterpret_cast<float2*>(C + (size_t)r0 * mCols + c) =
                    make_float2(acc[mi][nj][0] + b2v.x, acc[mi][nj][1] + b2v.y);
            int r1 = r0 + 8;
            if (r1 < N_NODES)
                *reinterpret_cast<float2*>(C + (size_t)r1 * mCols + c) =
                    make_float2(acc[mi][nj][2] + b2v.x, acc[mi][nj][3] + b2v.y);
        }
    }
}

// ---------------- GRU gates ----------------
__device__ __forceinline__ float sigf(float x) { return 1.f / (1.f + expf(-x)); }

__global__ void k_gate(const float* __restrict__ A, float* __restrict__ out) {
    int gid = blockIdx.x * blockDim.x + threadIdx.x;
    int node = gid >> 5, lane = gid & 31;
    if (node >= N_NODES) return;
    const float4* gi = reinterpret_cast<const float4*>(g_gi + (size_t)node * 384);
    const float4* gh = reinterpret_cast<const float4*>(g_gh + (size_t)node * 384);
    float4 gir = gi[lane], giz = gi[32 + lane], gin = gi[64 + lane];
    float4 ghr = gh[lane], ghz = gh[32 + lane], ghn = gh[64 + lane];
    float4 h = reinterpret_cast<const float4*>(A)[node * 32 + lane];
    float4 res;
    { float r = sigf(gir.x + ghr.x), z = sigf(giz.x + ghz.x);
      float n = tanhf(gin.x + r * ghn.x); res.x = (1.f - z) * n + z * h.x; }
    { float r = sigf(gir.y + ghr.y), z = sigf(giz.y + ghz.y);
      float n = tanhf(gin.y + r * ghn.y); res.y = (1.f - z) * n + z * h.y; }
    { float r = sigf(gir.z + ghr.z), z = sigf(giz.z + ghz.z);
      float n = tanhf(gin.z + r * ghn.z); res.z = (1.f - z) * n + z * h.z; }
    { float r = sigf(gir.w + ghr.w), z = sigf(giz.w + ghz.w);
      float n = tanhf(gin.w + r * ghn.w); res.w = (1.f - z) * n + z * h.w; }
    reinterpret_cast<float4*>(out)[node * 32 + lane] = res;
}

// ---------------- launch ----------------
extern "C" void kernel_launch(void* const* d_in, const int* in_sizes, int n_in,
                              void* d_out, int out_size) {
    const float* A    = (const float*)d_in[0];
    const float* W1   = (const float*)d_in[1];
    const float* b1   = (const float*)d_in[2];
    const float* W2   = (const float*)d_in[3];
    const float* b2   = (const float*)d_in[4];
    const float* w_ih = (const float*)d_in[5];
    const float* w_hh = (const float*)d_in[6];
    const float* b_ih = (const float*)d_in[7];
    const float* b_hh = (const float*)d_in[8];
    const void*  ei   = d_in[9];
    float* out = (float*)d_out;

    cudaFuncSetAttribute(k_hmma, cudaFuncAttributeMaxDynamicSharedMemorySize, SM_TOTAL);

    constexpr int RT = (N_NODES + 127) / 128;       // 782 row tiles
    constexpr int NODE_BLKS = (N_NODES + 255) / 256;
    constexpr int EDGE_BLKS = (N_EDGES + 255) / 256;
    constexpr int WARP_BLKS = (N_NODES * 32 + 255) / 256;
    constexpr int CVTA_BLKS = (N_NODES * 32 + 255) / 256;
    constexpr int CVTW_BLKS = ((128 + 384 + 384) * 32 + 255) / 256;

    k_zero<<<NODE_BLKS, 256>>>((const int*)ei);
    k_cvtA<<<CVTA_BLKS, 256>>>(A);
    k_cvtW<<<CVTW_BLKS, 256>>>(W2, w_ih, w_hh);
    k_hmma<<<dim3(RT, 1), 256, SM_TOTAL>>>(0, 0, b2, 0, 128);      // nft
    k_logits<<<WARP_BLKS, 256>>>(A, W1);
    k_count<<<EDGE_BLKS, 256>>>(ei);
    k_alloc<<<NODE_BLKS, 256>>>();
    k_fill<<<EDGE_BLKS, 256>>>(ei, b1);
    k_agg<<<WARP_BLKS, 256>>>(A);
    k_hmma<<<dim3(RT, 3), 256, SM_TOTAL>>>(1, 1, b_ih, 1, 384);    // gi
    k_hmma<<<dim3(RT, 3), 256, SM_TOTAL>>>(0, 2, b_hh, 2, 384);    // gh
    k_gate<<<WARP_BLKS, 256>>>(A, out);
}

// round 8
// speedup vs baseline: 2.2238x; 1.4042x over previous
#include <cuda_runtime.h>
#include <cuda_fp16.h>
#include <math.h>

static constexpr int N_NODES = 100000;
static constexpr int N_EDGES = 1600000;
static constexpr int D = 128;

// ---------------- scratch (device globals; no runtime allocation) ----------------
__device__ __align__(16) float g_nft[N_NODES * D];
__device__ __align__(16) float g_gi[N_NODES * 384];
__device__ __align__(16) float g_gh[N_NODES * 384];
__device__ __align__(16) __half g_ah[N_NODES * D];        // A in fp16 (RN)
__device__ __align__(16) __half g_oh[N_NODES * D];        // out_emb in fp16 (RN)
__device__ __align__(16) __half g_w2h[128 * D],  g_w2l[128 * D];    // W split hi/lo
__device__ __align__(16) __half g_wih_h[384 * D], g_wih_l[384 * D];
__device__ __align__(16) __half g_whh_h[384 * D], g_whh_l[384 * D];
__device__ float g_logit[N_NODES];
__device__ float g_logit_src[N_NODES];
__device__ int   g_cnt[N_NODES];
__device__ int   g_start[N_NODES];
__device__ int   g_cursor[N_NODES];
__device__ __align__(8) int2 g_pack[N_EDGES];             // {src, bits(exp(score))}
__device__ int   g_counter;
__device__ int   g_is64;

// ---------------- fp16 helpers ----------------
__device__ __forceinline__ void cvt4_h(float4 v, __half* dst, long long i4) {
    __half2 p0 = __floats2half2_rn(v.x, v.y);
    __half2 p1 = __floats2half2_rn(v.z, v.w);
    uint2 u;
    u.x = *reinterpret_cast<unsigned*>(&p0);
    u.y = *reinterpret_cast<unsigned*>(&p1);
    reinterpret_cast<uint2*>(dst)[i4] = u;
}
__device__ __forceinline__ void cvt4_hl(float4 v, __half* hi, __half* lo, long long i4) {
    __half h0 = __float2half(v.x), h1 = __float2half(v.y);
    __half h2 = __float2half(v.z), h3 = __float2half(v.w);
    float4 r = make_float4(v.x - __half2float(h0), v.y - __half2float(h1),
                           v.z - __half2float(h2), v.w - __half2float(h3));
    cvt4_h(v, hi, i4);
    cvt4_h(r, lo, i4);
}

// dtype-adaptive edge index load, clamped to [0, N_NODES).
__device__ __forceinline__ int load_idx(const void* ei, long long i, int is64) {
    long long v = is64 ? reinterpret_cast<const long long*>(ei)[i]
                       : (long long)reinterpret_cast<const int*>(ei)[i];
    v = v < 0 ? 0 : (v >= N_NODES ? N_NODES - 1 : v);
    return (int)v;
}

// ---------------- small kernels ----------------
__global__ void k_zero(const int* __restrict__ eiw) {
    int i = blockIdx.x * blockDim.x + threadIdx.x;
    if (i < N_NODES) g_cnt[i] = 0;
    if (i == 0) {
        g_counter = 0;
        g_is64 = (eiw[1] == 0 && eiw[3] == 0 && eiw[5] == 0 && eiw[7] == 0) ? 1 : 0;
    }
}

__global__ void k_cvtA(const float* __restrict__ A) {
    int i = blockIdx.x * blockDim.x + threadIdx.x;
    if (i >= N_NODES * 32) return;
    cvt4_h(reinterpret_cast<const float4*>(A)[i], g_ah, i);
}

__global__ void k_cvtW(const float* __restrict__ W2, const float* __restrict__ wih,
                       const float* __restrict__ whh) {
    int i = blockIdx.x * blockDim.x + threadIdx.x;
    const int n2 = 128 * 32, nih = 384 * 32;
    if (i < n2)
        cvt4_hl(reinterpret_cast<const float4*>(W2)[i], g_w2h, g_w2l, i);
    else if (i < n2 + nih)
        cvt4_hl(reinterpret_cast<const float4*>(wih)[i - n2], g_wih_h, g_wih_l, i - n2);
    else if (i < n2 + 2 * nih)
        cvt4_hl(reinterpret_cast<const float4*>(whh)[i - n2 - nih], g_whh_h, g_whh_l, i - n2 - nih);
}

__global__ void k_logits(const float* __restrict__ A, const float* __restrict__ W1) {
    int gid = blockIdx.x * blockDim.x + threadIdx.x;
    int node = gid >> 5, lane = gid & 31;
    if (node >= N_NODES) return;
    float4 x  = reinterpret_cast<const float4*>(A)[node * 32 + lane];
    float4 wd = __ldg(reinterpret_cast<const float4*>(W1) + lane);
    float4 ws = __ldg(reinterpret_cast<const float4*>(W1) + 32 + lane);
    float d = x.x * wd.x + x.y * wd.y + x.z * wd.z + x.w * wd.w;
    float s = x.x * ws.x + x.y * ws.y + x.z * ws.z + x.w * ws.w;
#pragma unroll
    for (int o = 16; o; o >>= 1) {
        d += __shfl_xor_sync(0xffffffffu, d, o);
        s += __shfl_xor_sync(0xffffffffu, s, o);
    }
    if (lane == 0) { g_logit[node] = d; g_logit_src[node] = s; }
}

__global__ void k_count(const void* __restrict__ ei) {
    int e = blockIdx.x * blockDim.x + threadIdx.x;
    if (e >= N_EDGES) return;
    atomicAdd(&g_cnt[load_idx(ei, (long long)N_EDGES + e, g_is64)], 1);
}

__global__ void k_alloc() {
    int n = blockIdx.x * blockDim.x + threadIdx.x;
    if (n >= N_NODES) return;
    int c = g_cnt[n];
    int s = atomicAdd(&g_counter, c);
    g_start[n] = s;
    g_cursor[n] = s;
}

// segment_max elided: cancels exactly in attn = e/denom; scores are O(1).
__global__ void k_fill(const void* __restrict__ ei, const float* __restrict__ b1) {
    int e = blockIdx.x * blockDim.x + threadIdx.x;
    if (e >= N_EDGES) return;
    int is64 = g_is64;
    int src = load_idx(ei, e, is64);
    int dst = load_idx(ei, (long long)N_EDGES + e, is64);
    float sc = g_logit[dst] + g_logit_src[src] + __ldg(b1);
    sc = sc > 0.f ? sc : 0.2f * sc;
    float es = expf(sc);
    int pos = atomicAdd(&g_cursor[dst], 1);
    if (pos < N_EDGES) g_pack[pos] = make_int2(src, __float_as_int(es));
}

// warp per node: denom + weighted gather + ELU + deg select; writes fp16 oemb
__global__ void k_agg(const float* __restrict__ A) {
    int gid = blockIdx.x * blockDim.x + threadIdx.x;
    int node = gid >> 5, lane = gid & 31;
    if (node >= N_NODES) return;
    int s0 = g_start[node];
    int len = g_cnt[node];
    if (s0 + len > N_EDGES) len = N_EDGES - s0 > 0 ? N_EDGES - s0 : 0;

    float dsum = 0.f;
    for (int t = lane; t < len; t += 32) dsum += __int_as_float(g_pack[s0 + t].y);
#pragma unroll
    for (int o = 16; o; o >>= 1) dsum += __shfl_xor_sync(0xffffffffu, dsum, o);

    float4 out;
    if (len > 0) {
        float inv = 1.f / dsum;
        float ax = 0.f, ay = 0.f, az = 0.f, aw = 0.f;
        const float4* nf = reinterpret_cast<const float4*>(g_nft);
#pragma unroll 2
        for (int t = 0; t < len; ++t) {
            int2 p = g_pack[s0 + t];
            float w = __int_as_float(p.y) * inv;
            float4 v = nf[(size_t)p.x * 32 + lane];
            ax = fmaf(w, v.x, ax); ay = fmaf(w, v.y, ay);
            az = fmaf(w, v.z, az); aw = fmaf(w, v.w, aw);
        }
        out.x = ax > 0.f ? ax : (expf(ax) - 1.f);
        out.y = ay > 0.f ? ay : (expf(ay) - 1.f);
        out.z = az > 0.f ? az : (expf(az) - 1.f);
        out.w = aw > 0.f ? aw : (expf(aw) - 1.f);
    } else {
        out = reinterpret_cast<const float4*>(A)[node * 32 + lane];
    }
    cvt4_h(out, g_oh, (long long)node * 32 + lane);
}

// ---------------- HMMA GEMM (mma.sync fp16, W split hi/lo, cp.async pipelined) ----
// C = X_fp16 . (Whi + Wlo)^T + bias ; error = (X - X_fp16).W ~ 2^-12 relative.
// 128x128 CTA tile, 8 warps (2x4), warp tile 64x32, m16n8k16.
// smem row = 256B (16 chunks of 16B), phys chunk = ch ^ (row&7).

static constexpr int SM_AH = 0;
static constexpr int SM_WH = 32768;
static constexpr int SM_WL = 65536;
static constexpr int SM_TOTAL = 98304;

__device__ __forceinline__ unsigned smem_u32(const void* p) {
    unsigned a;
    asm("{ .reg .u64 t; cvta.to.shared.u64 t, %1; cvt.u32.u64 %0, t; }" : "=r"(a) : "l"(p));
    return a;
}
__device__ __forceinline__ void cpasync16(unsigned dst, const void* src, bool valid) {
    int sz = valid ? 16 : 0;
    asm volatile("cp.async.cg.shared.global [%0], [%1], 16, %2;"
                 :: "r"(dst), "l"(src), "r"(sz) : "memory");
}
__device__ __forceinline__ void ldsm4(unsigned& r0, unsigned& r1, unsigned& r2, unsigned& r3, unsigned a) {
    asm volatile("ldmatrix.sync.aligned.m8n8.x4.shared.b16 {%0,%1,%2,%3}, [%4];"
                 : "=r"(r0), "=r"(r1), "=r"(r2), "=r"(r3) : "r"(a));
}
__device__ __forceinline__ void mma16816(float* c, unsigned a0, unsigned a1, unsigned a2, unsigned a3,
                                         unsigned b0, unsigned b1) {
    asm volatile("mma.sync.aligned.m16n8k16.row.col.f32.f16.f16.f32 "
                 "{%0,%1,%2,%3}, {%4,%5,%6,%7}, {%8,%9}, {%0,%1,%2,%3};"
                 : "+f"(c[0]), "+f"(c[1]), "+f"(c[2]), "+f"(c[3])
                 : "r"(a0), "r"(a1), "r"(a2), "r"(a3), "r"(b0), "r"(b1));
}

__global__ __launch_bounds__(256, 2) void k_hmma(
    int mode,                     // 0 = nft (grid RT x 1), 1 = merged gi/gh (grid RT x 6)
    const float* __restrict__ b2,
    const float* __restrict__ bih,
    const float* __restrict__ bhh)
{
    extern __shared__ __align__(128) char smem[];
    const int tid = threadIdx.x, wid = tid >> 5, lane = tid & 31;
    const unsigned sb = smem_u32(smem);
    const int rowBase = blockIdx.x * 128;

    const __half *Xp, *Whp, *Wlp;
    const float* bias;
    float* C;
    int mCols, colBase;
    if (mode == 0) {
        Xp = g_ah; Whp = g_w2h; Wlp = g_w2l; bias = b2; C = g_nft; mCols = 128; colBase = 0;
    } else {
        int y = blockIdx.y;
        if (y < 3) { Xp = g_oh; Whp = g_wih_h; Wlp = g_wih_l; bias = bih; C = g_gi; colBase = y * 128; }
        else       { Xp = g_ah; Whp = g_whh_h; Wlp = g_whh_l; bias = bhh; C = g_gh; colBase = (y - 3) * 128; }
        mCols = 384;
    }

    // ---- pipelined tile loads: group1 = {X, Whi}, group2 = {Wlo} ----
#pragma unroll
    for (int it = 0; it < 8; ++it) {
        int lc  = it * 256 + tid;        // 0..2047
        int row = lc >> 4;
        int ch  = lc & 15;
        unsigned so = (unsigned)(row * 256 + ((ch ^ (row & 7)) << 4));
        int gr = rowBase + row;
        cpasync16(sb + SM_AH + so, Xp + (size_t)gr * 128 + ch * 8, gr < N_NODES);
        cpasync16(sb + SM_WH + so, Whp + (size_t)(colBase + row) * 128 + ch * 8, true);
    }
    asm volatile("cp.async.commit_group;" ::: "memory");
#pragma unroll
    for (int it = 0; it < 8; ++it) {
        int lc  = it * 256 + tid;
        int row = lc >> 4;
        int ch  = lc & 15;
        unsigned so = (unsigned)(row * 256 + ((ch ^ (row & 7)) << 4));
        cpasync16(sb + SM_WL + so, Wlp + (size_t)(colBase + row) * 128 + ch * 8, true);
    }
    asm volatile("cp.async.commit_group;" ::: "memory");

    const int warpRow = (wid >> 2) * 64;   // 0 or 64
    const int warpCol = (wid & 3) * 32;    // 0,32,64,96
    const int arow = warpRow + (lane & 15);
    const int ahalf = lane >> 4;
    const int bn = warpCol + ((lane >> 4) << 3) + (lane & 7);
    const int bhalf = (lane >> 3) & 1;

    float acc[4][4][4];
#pragma unroll
    for (int mi = 0; mi < 4; ++mi)
#pragma unroll
        for (int nj = 0; nj < 4; ++nj)
#pragma unroll
            for (int q = 0; q < 4; ++q) acc[mi][nj][q] = 0.f;

#pragma unroll
    for (int t = 0; t < 2; ++t) {
        if (t == 0) { asm volatile("cp.async.wait_group 1;" ::: "memory"); }
        else        { asm volatile("cp.async.wait_group 0;" ::: "memory"); }
        __syncthreads();
        unsigned ab = sb + SM_AH;
        unsigned bb = sb + (t == 0 ? SM_WH : SM_WL);
#pragma unroll
        for (int s = 0; s < 8; ++s) {
            unsigned a[4][4];
#pragma unroll
            for (int mi = 0; mi < 4; ++mi) {
                int r = arow + mi * 16;
                unsigned ch = (unsigned)((2 * s + ahalf) ^ (r & 7));
                ldsm4(a[mi][0], a[mi][1], a[mi][2], a[mi][3], ab + r * 256 + (ch << 4));
            }
            unsigned b[2][4];
#pragma unroll
            for (int q = 0; q < 2; ++q) {
                int n = bn + q * 16;
                unsigned ch = (unsigned)((2 * s + bhalf) ^ (n & 7));
                ldsm4(b[q][0], b[q][1], b[q][2], b[q][3], bb + n * 256 + (ch << 4));
            }
#pragma unroll
            for (int mi = 0; mi < 4; ++mi) {
#pragma unroll
                for (int nj = 0; nj < 4; ++nj) {
                    unsigned b0 = b[nj >> 1][(nj & 1) * 2];
                    unsigned b1 = b[nj >> 1][(nj & 1) * 2 + 1];
                    mma16816(acc[mi][nj], a[mi][0], a[mi][1], a[mi][2], a[mi][3], b0, b1);
                }
            }
        }
    }

    // ---- epilogue: bias + direct STG ----
    const int colOff = colBase + warpCol + 2 * (lane & 3);
#pragma unroll
    for (int nj = 0; nj < 4; ++nj) {
        int c = colOff + nj * 8;
        float2 b2v = __ldg(reinterpret_cast<const float2*>(bias + c));
#pragma unroll
        for (int mi = 0; mi < 4; ++mi) {
            int r0 = rowBase + warpRow + mi * 16 + (lane >> 2);
            if (r0 < N_NODES)
                *reinterpret_cast<float2*>(C + (size_t)r0 * mCols + c) =
                    make_float2(acc[mi][nj][0] + b2v.x, acc[mi][nj][1] + b2v.y);
            int r1 = r0 + 8;
            if (r1 < N_NODES)
                *reinterpret_cast<float2*>(C + (size_t)r1 * mCols + c) =
                    make_float2(acc[mi][nj][2] + b2v.x, acc[mi][nj][3] + b2v.y);
        }
    }
}

// ---------------- GRU gates ----------------
__device__ __forceinline__ float sigf(float x) { return 1.f / (1.f + expf(-x)); }

__global__ void k_gate(const float* __restrict__ A, float* __restrict__ out) {
    int gid = blockIdx.x * blockDim.x + threadIdx.x;
    int node = gid >> 5, lane = gid & 31;
    if (node >= N_NODES) return;
    const float4* gi = reinterpret_cast<const float4*>(g_gi + (size_t)node * 384);
    const float4* gh = reinterpret_cast<const float4*>(g_gh + (size_t)node * 384);
    float4 gir = gi[lane], giz = gi[32 + lane], gin = gi[64 + lane];
    float4 ghr = gh[lane], ghz = gh[32 + lane], ghn = gh[64 + lane];
    float4 h = reinterpret_cast<const float4*>(A)[node * 32 + lane];
    float4 res;
    { float r = sigf(gir.x + ghr.x), z = sigf(giz.x + ghz.x);
      float n = tanhf(gin.x + r * ghn.x); res.x = (1.f - z) * n + z * h.x; }
    { float r = sigf(gir.y + ghr.y), z = sigf(giz.y + ghz.y);
      float n = tanhf(gin.y + r * ghn.y); res.y = (1.f - z) * n + z * h.y; }
    { float r = sigf(gir.z + ghr.z), z = sigf(giz.z + ghz.z);
      float n = tanhf(gin.z + r * ghn.z); res.z = (1.f - z) * n + z * h.z; }
    { float r = sigf(gir.w + ghr.w), z = sigf(giz.w + ghz.w);
      float n = tanhf(gin.w + r * ghn.w); res.w = (1.f - z) * n + z * h.w; }
    reinterpret_cast<float4*>(out)[node * 32 + lane] = res;
}

// ---------------- launch ----------------
extern "C" void kernel_launch(void* const* d_in, const int* in_sizes, int n_in,
                              void* d_out, int out_size) {
    const float* A    = (const float*)d_in[0];
    const float* W1   = (const float*)d_in[1];
    const float* b1   = (const float*)d_in[2];
    const float* W2   = (const float*)d_in[3];
    const float* b2   = (const float*)d_in[4];
    const float* w_ih = (const float*)d_in[5];
    const float* w_hh = (const float*)d_in[6];
    const float* b_ih = (const float*)d_in[7];
    const float* b_hh = (const float*)d_in[8];
    const void*  ei   = d_in[9];
    float* out = (float*)d_out;

    cudaFuncSetAttribute(k_hmma, cudaFuncAttributeMaxDynamicSharedMemorySize, SM_TOTAL);

    constexpr int RT = (N_NODES + 127) / 128;       // 782 row tiles
    constexpr int NODE_BLKS = (N_NODES + 255) / 256;
    constexpr int EDGE_BLKS = (N_EDGES + 255) / 256;
    constexpr int WARP_BLKS = (N_NODES * 32 + 255) / 256;
    constexpr int CVTA_BLKS = (N_NODES * 32 + 255) / 256;
    constexpr int CVTW_BLKS = ((128 + 384 + 384) * 32 + 255) / 256;

    k_zero<<<NODE_BLKS, 256>>>((const int*)ei);
    k_cvtA<<<CVTA_BLKS, 256>>>(A);
    k_cvtW<<<CVTW_BLKS, 256>>>(W2, w_ih, w_hh);
    k_hmma<<<dim3(RT, 1), 256, SM_TOTAL>>>(0, b2, b_ih, b_hh);    // nft
    k_logits<<<WARP_BLKS, 256>>>(A, W1);
    k_count<<<EDGE_BLKS, 256>>>(ei);
    k_alloc<<<NODE_BLKS, 256>>>();
    k_fill<<<EDGE_BLKS, 256>>>(ei, b1);
    k_agg<<<WARP_BLKS, 256>>>(A);
    k_hmma<<<dim3(RT, 6), 256, SM_TOTAL>>>(1, b2, b_ih, b_hh);    // gi + gh merged
    k_gate<<<WARP_BLKS, 256>>>(A, out);
}

// round 9
// speedup vs baseline: 2.5201x; 1.1333x over previous
#include <cuda_runtime.h>
#include <cuda_fp16.h>
#include <math.h>

static constexpr int N_NODES = 100000;
static constexpr int N_EDGES = 1600000;
static constexpr int D = 128;

// ---------------- scratch (device globals; no runtime allocation) ----------------
__device__ __align__(16) __half g_nft[N_NODES * D];       // fp16: A@W2^T + b2
__device__ __align__(16) __half g_gih[N_NODES * 384];     // fp16 gate pre-activations
__device__ __align__(16) __half g_ghh[N_NODES * 384];
__device__ __align__(16) __half g_ah[N_NODES * D];        // A in fp16 (RN)
__device__ __align__(16) __half g_oh[N_NODES * D];        // out_emb in fp16 (RN)
__device__ __align__(16) __half g_w2h[128 * D],  g_w2l[128 * D];    // W split hi/lo
__device__ __align__(16) __half g_wih_h[384 * D], g_wih_l[384 * D];
__device__ __align__(16) __half g_whh_h[384 * D], g_whh_l[384 * D];
__device__ float g_logit[N_NODES];
__device__ float g_logit_src[N_NODES];
__device__ int   g_cnt[N_NODES];
__device__ int   g_start[N_NODES];
__device__ int   g_cursor[N_NODES];
__device__ __align__(8) int2 g_pack[N_EDGES];             // {src, bits(exp(score))}
__device__ int   g_counter;
__device__ int   g_is64;

// ---------------- fp16 helpers ----------------
__device__ __forceinline__ void cvt4_h(float4 v, __half* dst, long long i4) {
    __half2 p0 = __floats2half2_rn(v.x, v.y);
    __half2 p1 = __floats2half2_rn(v.z, v.w);
    uint2 u;
    u.x = *reinterpret_cast<unsigned*>(&p0);
    u.y = *reinterpret_cast<unsigned*>(&p1);
    reinterpret_cast<uint2*>(dst)[i4] = u;
}
__device__ __forceinline__ void cvt4_hl(float4 v, __half* hi, __half* lo, long long i4) {
    __half h0 = __float2half(v.x), h1 = __float2half(v.y);
    __half h2 = __float2half(v.z), h3 = __float2half(v.w);
    float4 r = make_float4(v.x - __half2float(h0), v.y - __half2float(h1),
                           v.z - __half2float(h2), v.w - __half2float(h3));
    cvt4_h(v, hi, i4);
    cvt4_h(r, lo, i4);
}
__device__ __forceinline__ float4 h4_to_f4(uint2 u) {
    __half2 a = *reinterpret_cast<__half2*>(&u.x);
    __half2 b = *reinterpret_cast<__half2*>(&u.y);
    float2 fa = __half22float2(a), fb = __half22float2(b);
    return make_float4(fa.x, fa.y, fb.x, fb.y);
}

// dtype-adaptive edge index load, clamped to [0, N_NODES).
__device__ __forceinline__ int load_idx(const void* ei, long long i, int is64) {
    long long v = is64 ? reinterpret_cast<const long long*>(ei)[i]
                       : (long long)reinterpret_cast<const int*>(ei)[i];
    v = v < 0 ? 0 : (v >= N_NODES ? N_NODES - 1 : v);
    return (int)v;
}

// ---------------- small kernels ----------------
__global__ void k_zero(const int* __restrict__ eiw) {
    int i = blockIdx.x * blockDim.x + threadIdx.x;
    if (i < N_NODES) g_cnt[i] = 0;
    if (i == 0) {
        g_counter = 0;
        g_is64 = (eiw[1] == 0 && eiw[3] == 0 && eiw[5] == 0 && eiw[7] == 0) ? 1 : 0;
    }
}

__global__ void k_cvtW(const float* __restrict__ W2, const float* __restrict__ wih,
                       const float* __restrict__ whh) {
    int i = blockIdx.x * blockDim.x + threadIdx.x;
    const int n2 = 128 * 32, nih = 384 * 32;
    if (i < n2)
        cvt4_hl(reinterpret_cast<const float4*>(W2)[i], g_w2h, g_w2l, i);
    else if (i < n2 + nih)
        cvt4_hl(reinterpret_cast<const float4*>(wih)[i - n2], g_wih_h, g_wih_l, i - n2);
    else if (i < n2 + 2 * nih)
        cvt4_hl(reinterpret_cast<const float4*>(whh)[i - n2 - nih], g_whh_h, g_whh_l, i - n2 - nih);
}

// merged: per-node logits AND fp16 conversion of A (single pass over A)
__global__ void k_logits(const float* __restrict__ A, const float* __restrict__ W1) {
    int gid = blockIdx.x * blockDim.x + threadIdx.x;
    int node = gid >> 5, lane = gid & 31;
    if (node >= N_NODES) return;
    float4 x  = reinterpret_cast<const float4*>(A)[node * 32 + lane];
    cvt4_h(x, g_ah, (long long)node * 32 + lane);
    float4 wd = __ldg(reinterpret_cast<const float4*>(W1) + lane);
    float4 ws = __ldg(reinterpret_cast<const float4*>(W1) + 32 + lane);
    float d = x.x * wd.x + x.y * wd.y + x.z * wd.z + x.w * wd.w;
    float s = x.x * ws.x + x.y * ws.y + x.z * ws.z + x.w * ws.w;
#pragma unroll
    for (int o = 16; o; o >>= 1) {
        d += __shfl_xor_sync(0xffffffffu, d, o);
        s += __shfl_xor_sync(0xffffffffu, s, o);
    }
    if (lane == 0) { g_logit[node] = d; g_logit_src[node] = s; }
}

__global__ void k_count(const void* __restrict__ ei) {
    int e = blockIdx.x * blockDim.x + threadIdx.x;
    if (e >= N_EDGES) return;
    atomicAdd(&g_cnt[load_idx(ei, (long long)N_EDGES + e, g_is64)], 1);
}

__global__ void k_alloc() {
    int n = blockIdx.x * blockDim.x + threadIdx.x;
    if (n >= N_NODES) return;
    int c = g_cnt[n];
    int s = atomicAdd(&g_counter, c);
    g_start[n] = s;
    g_cursor[n] = s;
}

// segment_max elided: cancels exactly in attn = e/denom; scores are O(1).
__global__ void k_fill(const void* __restrict__ ei, const float* __restrict__ b1) {
    int e = blockIdx.x * blockDim.x + threadIdx.x;
    if (e >= N_EDGES) return;
    int is64 = g_is64;
    int src = load_idx(ei, e, is64);
    int dst = load_idx(ei, (long long)N_EDGES + e, is64);
    float sc = g_logit[dst] + g_logit_src[src] + __ldg(b1);
    sc = sc > 0.f ? sc : 0.2f * sc;
    float es = expf(sc);
    int pos = atomicAdd(&g_cursor[dst], 1);
    if (pos < N_EDGES) g_pack[pos] = make_int2(src, __float_as_int(es));
}

// warp per node: denom + weighted gather (fp16 nft) + ELU + deg select; writes fp16 oemb
__global__ void k_agg(const float* __restrict__ A) {
    int gid = blockIdx.x * blockDim.x + threadIdx.x;
    int node = gid >> 5, lane = gid & 31;
    if (node >= N_NODES) return;
    int s0 = g_start[node];
    int len = g_cnt[node];
    if (s0 + len > N_EDGES) len = N_EDGES - s0 > 0 ? N_EDGES - s0 : 0;

    float dsum = 0.f;
    for (int t = lane; t < len; t += 32) dsum += __int_as_float(g_pack[s0 + t].y);
#pragma unroll
    for (int o = 16; o; o >>= 1) dsum += __shfl_xor_sync(0xffffffffu, dsum, o);

    float4 out;
    if (len > 0) {
        float inv = 1.f / dsum;
        float ax = 0.f, ay = 0.f, az = 0.f, aw = 0.f;
        const uint2* nf = reinterpret_cast<const uint2*>(g_nft);
#pragma unroll 2
        for (int t = 0; t < len; ++t) {
            int2 p = g_pack[s0 + t];
            float w = __int_as_float(p.y) * inv;
            float4 v = h4_to_f4(nf[(size_t)p.x * 32 + lane]);
            ax = fmaf(w, v.x, ax); ay = fmaf(w, v.y, ay);
            az = fmaf(w, v.z, az); aw = fmaf(w, v.w, aw);
        }
        out.x = ax > 0.f ? ax : (expf(ax) - 1.f);
        out.y = ay > 0.f ? ay : (expf(ay) - 1.f);
        out.z = az > 0.f ? az : (expf(az) - 1.f);
        out.w = aw > 0.f ? aw : (expf(aw) - 1.f);
    } else {
        out = reinterpret_cast<const float4*>(A)[node * 32 + lane];
    }
    cvt4_h(out, g_oh, (long long)node * 32 + lane);
}

// ---------------- HMMA GEMM (mma.sync fp16, W split hi/lo, cp.async pipelined) ----
// C = X_fp16 . (Whi + Wlo)^T + bias ; fp16 output.
// 128x128 CTA tile, 8 warps (2x4), warp tile 64x32, m16n8k16.
// smem row = 256B (16 chunks of 16B), phys chunk = ch ^ (row&7).

static constexpr int SM_AH = 0;
static constexpr int SM_WH = 32768;
static constexpr int SM_WL = 65536;
static constexpr int SM_TOTAL = 98304;

__device__ __forceinline__ unsigned smem_u32(const void* p) {
    unsigned a;
    asm("{ .reg .u64 t; cvta.to.shared.u64 t, %1; cvt.u32.u64 %0, t; }" : "=r"(a) : "l"(p));
    return a;
}
__device__ __forceinline__ void cpasync16(unsigned dst, const void* src, bool valid) {
    int sz = valid ? 16 : 0;
    asm volatile("cp.async.cg.shared.global [%0], [%1], 16, %2;"
                 :: "r"(dst), "l"(src), "r"(sz) : "memory");
}
__device__ __forceinline__ void ldsm4(unsigned& r0, unsigned& r1, unsigned& r2, unsigned& r3, unsigned a) {
    asm volatile("ldmatrix.sync.aligned.m8n8.x4.shared.b16 {%0,%1,%2,%3}, [%4];"
                 : "=r"(r0), "=r"(r1), "=r"(r2), "=r"(r3) : "r"(a));
}
__device__ __forceinline__ void mma16816(float* c, unsigned a0, unsigned a1, unsigned a2, unsigned a3,
                                         unsigned b0, unsigned b1) {
    asm volatile("mma.sync.aligned.m16n8k16.row.col.f32.f16.f16.f32 "
                 "{%0,%1,%2,%3}, {%4,%5,%6,%7}, {%8,%9}, {%0,%1,%2,%3};"
                 : "+f"(c[0]), "+f"(c[1]), "+f"(c[2]), "+f"(c[3])
                 : "r"(a0), "r"(a1), "r"(a2), "r"(a3), "r"(b0), "r"(b1));
}

__global__ __launch_bounds__(256, 2) void k_hmma(
    int mode,                     // 0 = nft (grid RT x 1), 1 = merged gi/gh (grid RT x 6)
    const float* __restrict__ b2,
    const float* __restrict__ bih,
    const float* __restrict__ bhh)
{
    extern __shared__ __align__(128) char smem[];
    const int tid = threadIdx.x, wid = tid >> 5, lane = tid & 31;
    const unsigned sb = smem_u32(smem);
    const int rowBase = blockIdx.x * 128;

    const __half *Xp, *Whp, *Wlp;
    const float* bias;
    __half* C;
    int mCols, colBase;
    if (mode == 0) {
        Xp = g_ah; Whp = g_w2h; Wlp = g_w2l; bias = b2; C = g_nft; mCols = 128; colBase = 0;
    } else {
        int y = blockIdx.y;
        if (y < 3) { Xp = g_oh; Whp = g_wih_h; Wlp = g_wih_l; bias = bih; C = g_gih; colBase = y * 128; }
        else       { Xp = g_ah; Whp = g_whh_h; Wlp = g_whh_l; bias = bhh; C = g_ghh; colBase = (y - 3) * 128; }
        mCols = 384;
    }

    // ---- pipelined tile loads: group1 = {X, Whi}, group2 = {Wlo} ----
#pragma unroll
    for (int it = 0; it < 8; ++it) {
        int lc  = it * 256 + tid;        // 0..2047
        int row = lc >> 4;
        int ch  = lc & 15;
        unsigned so = (unsigned)(row * 256 + ((ch ^ (row & 7)) << 4));
        int gr = rowBase + row;
        cpasync16(sb + SM_AH + so, Xp + (size_t)gr * 128 + ch * 8, gr < N_NODES);
        cpasync16(sb + SM_WH + so, Whp + (size_t)(colBase + row) * 128 + ch * 8, true);
    }
    asm volatile("cp.async.commit_group;" ::: "memory");
#pragma unroll
    for (int it = 0; it < 8; ++it) {
        int lc  = it * 256 + tid;
        int row = lc >> 4;
        int ch  = lc & 15;
        unsigned so = (unsigned)(row * 256 + ((ch ^ (row & 7)) << 4));
        cpasync16(sb + SM_WL + so, Wlp + (size_t)(colBase + row) * 128 + ch * 8, true);
    }
    asm volatile("cp.async.commit_group;" ::: "memory");

    const int warpRow = (wid >> 2) * 64;   // 0 or 64
    const int warpCol = (wid & 3) * 32;    // 0,32,64,96
    const int arow = warpRow + (lane & 15);
    const int ahalf = lane >> 4;
    const int bn = warpCol + ((lane >> 4) << 3) + (lane & 7);
    const int bhalf = (lane >> 3) & 1;

    float acc[4][4][4];
#pragma unroll
    for (int mi = 0; mi < 4; ++mi)
#pragma unroll
        for (int nj = 0; nj < 4; ++nj)
#pragma unroll
            for (int q = 0; q < 4; ++q) acc[mi][nj][q] = 0.f;

#pragma unroll
    for (int t = 0; t < 2; ++t) {
        if (t == 0) { asm volatile("cp.async.wait_group 1;" ::: "memory"); }
        else        { asm volatile("cp.async.wait_group 0;" ::: "memory"); }
        __syncthreads();
        unsigned ab = sb + SM_AH;
        unsigned bb = sb + (t == 0 ? SM_WH : SM_WL);
#pragma unroll
        for (int s = 0; s < 8; ++s) {
            unsigned a[4][4];
#pragma unroll
            for (int mi = 0; mi < 4; ++mi) {
                int r = arow + mi * 16;
                unsigned ch = (unsigned)((2 * s + ahalf) ^ (r & 7));
                ldsm4(a[mi][0], a[mi][1], a[mi][2], a[mi][3], ab + r * 256 + (ch << 4));
            }
            unsigned b[2][4];
#pragma unroll
            for (int q = 0; q < 2; ++q) {
                int n = bn + q * 16;
                unsigned ch = (unsigned)((2 * s + bhalf) ^ (n & 7));
                ldsm4(b[q][0], b[q][1], b[q][2], b[q][3], bb + n * 256 + (ch << 4));
            }
#pragma unroll
            for (int mi = 0; mi < 4; ++mi) {
#pragma unroll
                for (int nj = 0; nj < 4; ++nj) {
                    unsigned b0 = b[nj >> 1][(nj & 1) * 2];
                    unsigned b1 = b[nj >> 1][(nj & 1) * 2 + 1];
                    mma16816(acc[mi][nj], a[mi][0], a[mi][1], a[mi][2], a[mi][3], b0, b1);
                }
            }
        }
    }

    // ---- epilogue: bias + fp16 store ----
    const int colOff = colBase + warpCol + 2 * (lane & 3);
#pragma unroll
    for (int nj = 0; nj < 4; ++nj) {
        int c = colOff + nj * 8;
        float2 b2v = __ldg(reinterpret_cast<const float2*>(bias + c));
#pragma unroll
        for (int mi = 0; mi < 4; ++mi) {
            int r0 = rowBase + warpRow + mi * 16 + (lane >> 2);
            if (r0 < N_NODES) {
                __half2 h = __floats2half2_rn(acc[mi][nj][0] + b2v.x, acc[mi][nj][1] + b2v.y);
                *reinterpret_cast<unsigned*>(C + (size_t)r0 * mCols + c) = *reinterpret_cast<unsigned*>(&h);
            }
            int r1 = r0 + 8;
            if (r1 < N_NODES) {
                __half2 h = __floats2half2_rn(acc[mi][nj][2] + b2v.x, acc[mi][nj][3] + b2v.y);
                *reinterpret_cast<unsigned*>(C + (size_t)r1 * mCols + c) = *reinterpret_cast<unsigned*>(&h);
            }
        }
    }
}

// ---------------- GRU gates (fp16 inputs) ----------------
__device__ __forceinline__ float sigf(float x) { return 1.f / (1.f + expf(-x)); }

__global__ void k_gate(const float* __restrict__ A, float* __restrict__ out) {
    int gid = blockIdx.x * blockDim.x + threadIdx.x;
    int node = gid >> 5, lane = gid & 31;
    if (node >= N_NODES) return;
    const uint2* gi = reinterpret_cast<const uint2*>(g_gih + (size_t)node * 384);
    const uint2* gh = reinterpret_cast<const uint2*>(g_ghh + (size_t)node * 384);
    float4 gir = h4_to_f4(gi[lane]), giz = h4_to_f4(gi[32 + lane]), gin = h4_to_f4(gi[64 + lane]);
    float4 ghr = h4_to_f4(gh[lane]), ghz = h4_to_f4(gh[32 + lane]), ghn = h4_to_f4(gh[64 + lane]);
    float4 h = reinterpret_cast<const float4*>(A)[node * 32 + lane];
    float4 res;
    { float r = sigf(gir.x + ghr.x), z = sigf(giz.x + ghz.x);
      float n = tanhf(gin.x + r * ghn.x); res.x = (1.f - z) * n + z * h.x; }
    { float r = sigf(gir.y + ghr.y), z = sigf(giz.y + ghz.y);
      float n = tanhf(gin.y + r * ghn.y); res.y = (1.f - z) * n + z * h.y; }
    { float r = sigf(gir.z + ghr.z), z = sigf(giz.z + ghz.z);
      float n = tanhf(gin.z + r * ghn.z); res.z = (1.f - z) * n + z * h.z; }
    { float r = sigf(gir.w + ghr.w), z = sigf(giz.w + ghz.w);
      float n = tanhf(gin.w + r * ghn.w); res.w = (1.f - z) * n + z * h.w; }
    reinterpret_cast<float4*>(out)[node * 32 + lane] = res;
}

// ---------------- launch ----------------
extern "C" void kernel_launch(void* const* d_in, const int* in_sizes, int n_in,
                              void* d_out, int out_size) {
    const float* A    = (const float*)d_in[0];
    const float* W1   = (const float*)d_in[1];
    const float* b1   = (const float*)d_in[2];
    const float* W2   = (const float*)d_in[3];
    const float* b2   = (const float*)d_in[4];
    const float* w_ih = (const float*)d_in[5];
    const float* w_hh = (const float*)d_in[6];
    const float* b_ih = (const float*)d_in[7];
    const float* b_hh = (const float*)d_in[8];
    const void*  ei   = d_in[9];
    float* out = (float*)d_out;

    cudaFuncSetAttribute(k_hmma, cudaFuncAttributeMaxDynamicSharedMemorySize, SM_TOTAL);

    constexpr int RT = (N_NODES + 127) / 128;       // 782 row tiles
    constexpr int NODE_BLKS = (N_NODES + 255) / 256;
    constexpr int EDGE_BLKS = (N_EDGES + 255) / 256;
    constexpr int WARP_BLKS = (N_NODES * 32 + 255) / 256;
    constexpr int CVTW_BLKS = ((128 + 384 + 384) * 32 + 255) / 256;

    k_zero<<<NODE_BLKS, 256>>>((const int*)ei);
    k_logits<<<WARP_BLKS, 256>>>(A, W1);                          // also produces g_ah
    k_cvtW<<<CVTW_BLKS, 256>>>(W2, w_ih, w_hh);
    k_hmma<<<dim3(RT, 1), 256, SM_TOTAL>>>(0, b2, b_ih, b_hh);    // nft (fp16)
    k_count<<<EDGE_BLKS, 256>>>(ei);
    k_alloc<<<NODE_BLKS, 256>>>();
    k_fill<<<EDGE_BLKS, 256>>>(ei, b1);
    k_agg<<<WARP_BLKS, 256>>>(A);
    k_hmma<<<dim3(RT, 6), 256, SM_TOTAL>>>(1, b2, b_ih, b_hh);    // gi + gh merged (fp16)
    k_gate<<<WARP_BLKS, 256>>>(A, out);
}

// round 10
// speedup vs baseline: 2.9033x; 1.1520x over previous
#include <cuda_runtime.h>
#include <cuda_fp16.h>
#include <math.h>

static constexpr int N_NODES = 100000;
static constexpr int N_EDGES = 1600000;
static constexpr int D = 128;

// ---------------- scratch (device globals; no runtime allocation) ----------------
__device__ __align__(16) __half g_nft[N_NODES * D];       // fp16: A@W2^T + b2
__device__ __align__(16) __half g_gih[N_NODES * 384];     // fp16 gate pre-activations
__device__ __align__(16) __half g_ghh[N_NODES * 384];
__device__ __align__(16) __half g_ah[N_NODES * D];        // A in fp16 (RN)
__device__ __align__(16) __half g_oh[N_NODES * D];        // out_emb in fp16 (RN)
__device__ __align__(16) __half g_w2[128 * D];            // weights fp16
__device__ __align__(16) __half g_wih[384 * D];
__device__ __align__(16) __half g_whh[384 * D];
__device__ float g_logit[N_NODES];
__device__ float g_logit_src[N_NODES];
__device__ int   g_cnt[N_NODES];
__device__ int   g_start[N_NODES];
__device__ int   g_cursor[N_NODES];
__device__ __align__(8) int2 g_pack[N_EDGES];             // {src, bits(exp(score))}
__device__ int   g_counter;
__device__ int   g_is64;

// ---------------- fp16 helpers ----------------
__device__ __forceinline__ void cvt4_h(float4 v, __half* dst, long long i4) {
    __half2 p0 = __floats2half2_rn(v.x, v.y);
    __half2 p1 = __floats2half2_rn(v.z, v.w);
    uint2 u;
    u.x = *reinterpret_cast<unsigned*>(&p0);
    u.y = *reinterpret_cast<unsigned*>(&p1);
    reinterpret_cast<uint2*>(dst)[i4] = u;
}
__device__ __forceinline__ float4 h4_to_f4(uint2 u) {
    __half2 a = *reinterpret_cast<__half2*>(&u.x);
    __half2 b = *reinterpret_cast<__half2*>(&u.y);
    float2 fa = __half22float2(a), fb = __half22float2(b);
    return make_float4(fa.x, fa.y, fb.x, fb.y);
}

// dtype-adaptive edge index load, clamped to [0, N_NODES).
__device__ __forceinline__ int load_idx(const void* ei, long long i, int is64) {
    long long v = is64 ? reinterpret_cast<const long long*>(ei)[i]
                       : (long long)reinterpret_cast<const int*>(ei)[i];
    v = v < 0 ? 0 : (v >= N_NODES ? N_NODES - 1 : v);
    return (int)v;
}

// ---------------- small kernels ----------------
__global__ void k_zero(const int* __restrict__ eiw) {
    int i = blockIdx.x * blockDim.x + threadIdx.x;
    if (i < N_NODES) g_cnt[i] = 0;
    if (i == 0) {
        g_counter = 0;
        g_is64 = (eiw[1] == 0 && eiw[3] == 0 && eiw[5] == 0 && eiw[7] == 0) ? 1 : 0;
    }
}

__global__ void k_cvtW(const float* __restrict__ W2, const float* __restrict__ wih,
                       const float* __restrict__ whh) {
    int i = blockIdx.x * blockDim.x + threadIdx.x;
    const int n2 = 128 * 32, nih = 384 * 32;
    if (i < n2)
        cvt4_h(reinterpret_cast<const float4*>(W2)[i], g_w2, i);
    else if (i < n2 + nih)
        cvt4_h(reinterpret_cast<const float4*>(wih)[i - n2], g_wih, i - n2);
    else if (i < n2 + 2 * nih)
        cvt4_h(reinterpret_cast<const float4*>(whh)[i - n2 - nih], g_whh, i - n2 - nih);
}

// merged: per-node logits AND fp16 conversion of A (single pass over A)
__global__ void k_logits(const float* __restrict__ A, const float* __restrict__ W1) {
    int gid = blockIdx.x * blockDim.x + threadIdx.x;
    int node = gid >> 5, lane = gid & 31;
    if (node >= N_NODES) return;
    float4 x  = reinterpret_cast<const float4*>(A)[node * 32 + lane];
    cvt4_h(x, g_ah, (long long)node * 32 + lane);
    float4 wd = __ldg(reinterpret_cast<const float4*>(W1) + lane);
    float4 ws = __ldg(reinterpret_cast<const float4*>(W1) + 32 + lane);
    float d = x.x * wd.x + x.y * wd.y + x.z * wd.z + x.w * wd.w;
    float s = x.x * ws.x + x.y * ws.y + x.z * ws.z + x.w * ws.w;
#pragma unroll
    for (int o = 16; o; o >>= 1) {
        d += __shfl_xor_sync(0xffffffffu, d, o);
        s += __shfl_xor_sync(0xffffffffu, s, o);
    }
    if (lane == 0) { g_logit[node] = d; g_logit_src[node] = s; }
}

__global__ void k_count(const void* __restrict__ ei) {
    int e = blockIdx.x * blockDim.x + threadIdx.x;
    if (e >= N_EDGES) return;
    atomicAdd(&g_cnt[load_idx(ei, (long long)N_EDGES + e, g_is64)], 1);
}

__global__ void k_alloc() {
    int n = blockIdx.x * blockDim.x + threadIdx.x;
    if (n >= N_NODES) return;
    int c = g_cnt[n];
    int s = atomicAdd(&g_counter, c);
    g_start[n] = s;
    g_cursor[n] = s;
}

// segment_max elided: cancels exactly in attn = e/denom; scores are O(1).
__global__ void k_fill(const void* __restrict__ ei, const float* __restrict__ b1) {
    int e = blockIdx.x * blockDim.x + threadIdx.x;
    if (e >= N_EDGES) return;
    int is64 = g_is64;
    int src = load_idx(ei, e, is64);
    int dst = load_idx(ei, (long long)N_EDGES + e, is64);
    float sc = g_logit[dst] + g_logit_src[src] + __ldg(b1);
    sc = sc > 0.f ? sc : 0.2f * sc;
    float es = expf(sc);
    int pos = atomicAdd(&g_cursor[dst], 1);
    if (pos < N_EDGES) g_pack[pos] = make_int2(src, __float_as_int(es));
}

// warp per node: denom + weighted gather (fp16 nft) + ELU + deg select; writes fp16 oemb
__global__ void k_agg(const float* __restrict__ A) {
    int gid = blockIdx.x * blockDim.x + threadIdx.x;
    int node = gid >> 5, lane = gid & 31;
    if (node >= N_NODES) return;
    int s0 = g_start[node];
    int len = g_cnt[node];
    if (s0 + len > N_EDGES) len = N_EDGES - s0 > 0 ? N_EDGES - s0 : 0;

    float dsum = 0.f;
    for (int t = lane; t < len; t += 32) dsum += __int_as_float(g_pack[s0 + t].y);
#pragma unroll
    for (int o = 16; o; o >>= 1) dsum += __shfl_xor_sync(0xffffffffu, dsum, o);

    float4 out;
    if (len > 0) {
        float inv = 1.f / dsum;
        float ax = 0.f, ay = 0.f, az = 0.f, aw = 0.f;
        const uint2* nf = reinterpret_cast<const uint2*>(g_nft);
#pragma unroll 2
        for (int t = 0; t < len; ++t) {
            int2 p = g_pack[s0 + t];
            float w = __int_as_float(p.y) * inv;
            float4 v = h4_to_f4(nf[(size_t)p.x * 32 + lane]);
            ax = fmaf(w, v.x, ax); ay = fmaf(w, v.y, ay);
            az = fmaf(w, v.z, az); aw = fmaf(w, v.w, aw);
        }
        out.x = ax > 0.f ? ax : (expf(ax) - 1.f);
        out.y = ay > 0.f ? ay : (expf(ay) - 1.f);
        out.z = az > 0.f ? az : (expf(az) - 1.f);
        out.w = aw > 0.f ? aw : (expf(aw) - 1.f);
    } else {
        out = reinterpret_cast<const float4*>(A)[node * 32 + lane];
    }
    cvt4_h(out, g_oh, (long long)node * 32 + lane);
}

// ---------------- HMMA GEMM (plain fp16 mma.sync, cp.async, single term) ----
// C = X_fp16 . W_fp16^T + bias ; fp16 output. err ~2^-12 relative (within 1e-3 budget).
// 128x128 CTA tile, 8 warps (2x4), warp tile 64x32, m16n8k16.
// smem row = 256B (16 chunks of 16B), phys chunk = ch ^ (row&7).

static constexpr int SM_AH = 0;
static constexpr int SM_W  = 32768;
static constexpr int SM_TOTAL = 65536;

__device__ __forceinline__ unsigned smem_u32(const void* p) {
    unsigned a;
    asm("{ .reg .u64 t; cvta.to.shared.u64 t, %1; cvt.u32.u64 %0, t; }" : "=r"(a) : "l"(p));
    return a;
}
__device__ __forceinline__ void cpasync16(unsigned dst, const void* src, bool valid) {
    int sz = valid ? 16 : 0;
    asm volatile("cp.async.cg.shared.global [%0], [%1], 16, %2;"
                 :: "r"(dst), "l"(src), "r"(sz) : "memory");
}
__device__ __forceinline__ void ldsm4(unsigned& r0, unsigned& r1, unsigned& r2, unsigned& r3, unsigned a) {
    asm volatile("ldmatrix.sync.aligned.m8n8.x4.shared.b16 {%0,%1,%2,%3}, [%4];"
                 : "=r"(r0), "=r"(r1), "=r"(r2), "=r"(r3) : "r"(a));
}
__device__ __forceinline__ void mma16816(float* c, unsigned a0, unsigned a1, unsigned a2, unsigned a3,
                                         unsigned b0, unsigned b1) {
    asm volatile("mma.sync.aligned.m16n8k16.row.col.f32.f16.f16.f32 "
                 "{%0,%1,%2,%3}, {%4,%5,%6,%7}, {%8,%9}, {%0,%1,%2,%3};"
                 : "+f"(c[0]), "+f"(c[1]), "+f"(c[2]), "+f"(c[3])
                 : "r"(a0), "r"(a1), "r"(a2), "r"(a3), "r"(b0), "r"(b1));
}

__global__ __launch_bounds__(256, 2) void k_hmma(
    int mode,                     // 0 = nft+gh (grid RT x 4), 1 = gi (grid RT x 3)
    const float* __restrict__ b2,
    const float* __restrict__ bih,
    const float* __restrict__ bhh)
{
    extern __shared__ __align__(128) char smem[];
    const int tid = threadIdx.x, wid = tid >> 5, lane = tid & 31;
    const unsigned sb = smem_u32(smem);
    const int rowBase = blockIdx.x * 128;

    const __half *Xp, *Wp;
    const float* bias;
    __half* C;
    int mCols, colBase;
    if (mode == 0) {
        int y = blockIdx.y;
        if (y == 0) { Xp = g_ah; Wp = g_w2;  bias = b2;  C = g_nft; mCols = 128; colBase = 0; }
        else        { Xp = g_ah; Wp = g_whh; bias = bhh; C = g_ghh; mCols = 384; colBase = (y - 1) * 128; }
    } else {
        Xp = g_oh; Wp = g_wih; bias = bih; C = g_gih; mCols = 384; colBase = blockIdx.y * 128;
    }

    // ---- tile loads: X and W in one async group ----
#pragma unroll
    for (int it = 0; it < 8; ++it) {
        int lc  = it * 256 + tid;        // 0..2047
        int row = lc >> 4;
        int ch  = lc & 15;
        unsigned so = (unsigned)(row * 256 + ((ch ^ (row & 7)) << 4));
        int gr = rowBase + row;
        cpasync16(sb + SM_AH + so, Xp + (size_t)gr * 128 + ch * 8, gr < N_NODES);
        cpasync16(sb + SM_W  + so, Wp + (size_t)(colBase + row) * 128 + ch * 8, true);
    }
    asm volatile("cp.async.commit_group;" ::: "memory");

    const int warpRow = (wid >> 2) * 64;   // 0 or 64
    const int warpCol = (wid & 3) * 32;    // 0,32,64,96
    const int arow = warpRow + (lane & 15);
    const int ahalf = lane >> 4;
    const int bn = warpCol + ((lane >> 4) << 3) + (lane & 7);
    const int bhalf = (lane >> 3) & 1;

    float acc[4][4][4];
#pragma unroll
    for (int mi = 0; mi < 4; ++mi)
#pragma unroll
        for (int nj = 0; nj < 4; ++nj)
#pragma unroll
            for (int q = 0; q < 4; ++q) acc[mi][nj][q] = 0.f;

    asm volatile("cp.async.wait_group 0;" ::: "memory");
    __syncthreads();

    const unsigned ab = sb + SM_AH;
    const unsigned bb = sb + SM_W;
#pragma unroll
    for (int s = 0; s < 8; ++s) {
        unsigned a[4][4];
#pragma unroll
        for (int mi = 0; mi < 4; ++mi) {
            int r = arow + mi * 16;
            unsigned ch = (unsigned)((2 * s + ahalf) ^ (r & 7));
            ldsm4(a[mi][0], a[mi][1], a[mi][2], a[mi][3], ab + r * 256 + (ch << 4));
        }
        unsigned b[2][4];
#pragma unroll
        for (int q = 0; q < 2; ++q) {
            int n = bn + q * 16;
            unsigned ch = (unsigned)((2 * s + bhalf) ^ (n & 7));
            ldsm4(b[q][0], b[q][1], b[q][2], b[q][3], bb + n * 256 + (ch << 4));
        }
#pragma unroll
        for (int mi = 0; mi < 4; ++mi) {
#pragma unroll
            for (int nj = 0; nj < 4; ++nj) {
                unsigned b0 = b[nj >> 1][(nj & 1) * 2];
                unsigned b1 = b[nj >> 1][(nj & 1) * 2 + 1];
                mma16816(acc[mi][nj], a[mi][0], a[mi][1], a[mi][2], a[mi][3], b0, b1);
            }
        }
    }

    // ---- epilogue: bias + fp16 store ----
    const int colOff = colBase + warpCol + 2 * (lane & 3);
#pragma unroll
    for (int nj = 0; nj < 4; ++nj) {
        int c = colOff + nj * 8;
        float2 b2v = __ldg(reinterpret_cast<const float2*>(bias + c));
#pragma unroll
        for (int mi = 0; mi < 4; ++mi) {
            int r0 = rowBase + warpRow + mi * 16 + (lane >> 2);
            if (r0 < N_NODES) {
                __half2 h = __floats2half2_rn(acc[mi][nj][0] + b2v.x, acc[mi][nj][1] + b2v.y);
                *reinterpret_cast<unsigned*>(C + (size_t)r0 * mCols + c) = *reinterpret_cast<unsigned*>(&h);
            }
            int r1 = r0 + 8;
            if (r1 < N_NODES) {
                __half2 h = __floats2half2_rn(acc[mi][nj][2] + b2v.x, acc[mi][nj][3] + b2v.y);
                *reinterpret_cast<unsigned*>(C + (size_t)r1 * mCols + c) = *reinterpret_cast<unsigned*>(&h);
            }
        }
    }
}

// ---------------- GRU gates (fp16 inputs) ----------------
__device__ __forceinline__ float sigf(float x) { return 1.f / (1.f + expf(-x)); }

__global__ void k_gate(const float* __restrict__ A, float* __restrict__ out) {
    int gid = blockIdx.x * blockDim.x + threadIdx.x;
    int node = gid >> 5, lane = gid & 31;
    if (node >= N_NODES) return;
    const uint2* gi = reinterpret_cast<const uint2*>(g_gih + (size_t)node * 384);
    const uint2* gh = reinterpret_cast<const uint2*>(g_ghh + (size_t)node * 384);
    float4 gir = h4_to_f4(gi[lane]), giz = h4_to_f4(gi[32 + lane]), gin = h4_to_f4(gi[64 + lane]);
    float4 ghr = h4_to_f4(gh[lane]), ghz = h4_to_f4(gh[32 + lane]), ghn = h4_to_f4(gh[64 + lane]);
    float4 h = reinterpret_cast<const float4*>(A)[node * 32 + lane];
    float4 res;
    { float r = sigf(gir.x + ghr.x), z = sigf(giz.x + ghz.x);
      float n = tanhf(gin.x + r * ghn.x); res.x = (1.f - z) * n + z * h.x; }
    { float r = sigf(gir.y + ghr.y), z = sigf(giz.y + ghz.y);
      float n = tanhf(gin.y + r * ghn.y); res.y = (1.f - z) * n + z * h.y; }
    { float r = sigf(gir.z + ghr.z), z = sigf(giz.z + ghz.z);
      float n = tanhf(gin.z + r * ghn.z); res.z = (1.f - z) * n + z * h.z; }
    { float r = sigf(gir.w + ghr.w), z = sigf(giz.w + ghz.w);
      float n = tanhf(gin.w + r * ghn.w); res.w = (1.f - z) * n + z * h.w; }
    reinterpret_cast<float4*>(out)[node * 32 + lane] = res;
}

// ---------------- launch ----------------
extern "C" void kernel_launch(void* const* d_in, const int* in_sizes, int n_in,
                              void* d_out, int out_size) {
    const float* A    = (const float*)d_in[0];
    const float* W1   = (const float*)d_in[1];
    const float* b1   = (const float*)d_in[2];
    const float* W2   = (const float*)d_in[3];
    const float* b2   = (const float*)d_in[4];
    const float* w_ih = (const float*)d_in[5];
    const float* w_hh = (const float*)d_in[6];
    const float* b_ih = (const float*)d_in[7];
    const float* b_hh = (const float*)d_in[8];
    const void*  ei   = d_in[9];
    float* out = (float*)d_out;

    cudaFuncSetAttribute(k_hmma, cudaFuncAttributeMaxDynamicSharedMemorySize, SM_TOTAL);

    constexpr int RT = (N_NODES + 127) / 128;       // 782 row tiles
    constexpr int NODE_BLKS = (N_NODES + 255) / 256;
    constexpr int EDGE_BLKS = (N_EDGES + 255) / 256;
    constexpr int WARP_BLKS = (N_NODES * 32 + 255) / 256;
    constexpr int CVTW_BLKS = ((128 + 384 + 384) * 32 + 255) / 256;

    k_zero<<<NODE_BLKS, 256>>>((const int*)ei);
    k_logits<<<WARP_BLKS, 256>>>(A, W1);                          // also produces g_ah
    k_cvtW<<<CVTW_BLKS, 256>>>(W2, w_ih, w_hh);
    k_hmma<<<dim3(RT, 4), 256, SM_TOTAL>>>(0, b2, b_ih, b_hh);    // nft + gh (gh independent of edges)
    k_count<<<EDGE_BLKS, 256>>>(ei);
    k_alloc<<<NODE_BLKS, 256>>>();
    k_fill<<<EDGE_BLKS, 256>>>(ei, b1);
    k_agg<<<WARP_BLKS, 256>>>(A);
    k_hmma<<<dim3(RT, 3), 256, SM_TOTAL>>>(1, b2, b_ih, b_hh);    // gi
    k_gate<<<WARP_BLKS, 256>>>(A, out);
}